// round 5
// baseline (speedup 1.0000x reference)
#include <cuda_runtime.h>
#include <math.h>

#define Bn 12
#define HW1 45056           // 128*352
#define N5 11264            // 64*176
#define W5i 176
#define BEVC 64
#define OUT_MAIN (12*128*128*128)   // 25165824

#define ROLEW_BLKS 64
#define ROLEB_BLKS (Bn*88)          // 1056
#define ROLEA_BLKS (Bn*HW1/256)     // 2112

typedef unsigned long long u64;

// packed f32x2 helpers (sm_103a)
__device__ __forceinline__ u64 pack2(float lo, float hi) {
    u64 r; asm("mov.b64 %0, {%1, %2};" : "=l"(r) : "f"(lo), "f"(hi)); return r;
}
__device__ __forceinline__ void fma2(u64 &d, u64 a, u64 b) {
    asm("fma.rn.f32x2 %0, %1, %2, %0;" : "+l"(d) : "l"(a), "l"(b));
}
__device__ __forceinline__ float2 unpack2(u64 v) {
    float2 r; asm("mov.b64 {%0, %1}, %2;" : "=f"(r.x), "=f"(r.y) : "l"(v)); return r;
}

// BEV scratch, channels-last: [B][128][128][64]
__device__ float g_bev[Bn * 128 * 128 * BEVC];
__device__ int   g_sidx[Bn * N5];
__device__ float g_swf [Bn * N5];
// transposed conv weights: [kk 9][ic 64][oc 128]
__device__ float g_wt[9 * 64 * 128];

// ---------------------------------------------------------------------------
// Fused kernel 1: three independent roles co-resident in one launch.
//   role W: transpose main conv weights into g_wt
//   role B: depth head -> g_sidx / g_swf
//   role A: skip path
// ---------------------------------------------------------------------------
struct SmemA {
    float w1T[64*64];
    float w2T[64*32];
    float sg1[64], sb1[64], sg2[32], sb2[32];
};
struct SmemB {
    float ws[64*48];
    float sgd[48], sbd[48];
};
union SmemU { SmemA a; SmemB b; };

__device__ void roleW(int bid, int tid, const float* __restrict__ w)
{
    // g_wt[(kk*64+ic)*128 + oc] = w[(oc*64+ic)*9 + kk]
    for (int i = bid * 128 + tid; i < 9*64*128; i += ROLEW_BLKS * 128) {
        int oc = i & 127;
        int t  = i >> 7;
        int ic = t & 63;
        int kk = t >> 6;
        g_wt[i] = w[(oc*64 + ic)*9 + kk];
    }
}

__device__ void roleB(int bid, int tid, SmemB& s,
                      const float* __restrict__ stage5,
                      const float* __restrict__ wd, const float* __restrict__ gd,
                      const float* __restrict__ bd,
                      const float* __restrict__ intr, const float* __restrict__ extr)
{
    if (tid < 48) { s.sgd[tid] = gd[tid]; s.sbd[tid] = bd[tid]; }
    int b = bid / 88;
    int p = (bid - b * 88) * 128 + tid;
    const float* xin = stage5 + (size_t)b * 512 * N5 + p;

    u64 acc2[24];
    #pragma unroll
    for (int i = 0; i < 24; i++) acc2[i] = 0ull;

    for (int c0 = 0; c0 < 512; c0 += 64) {
        __syncthreads();
        for (int i = tid; i < 64*48; i += 128) {
            int o = i % 48; int c = i / 48;
            s.ws[c*48 + o] = wd[o*512 + c0 + c];
        }
        __syncthreads();
        const ulonglong2* ws2 = (const ulonglong2*)s.ws;
        for (int c = 0; c < 64; c++) {
            float xv = xin[(size_t)(c0 + c) * N5];
            u64 xv2 = pack2(xv, xv);
            #pragma unroll
            for (int q = 0; q < 12; q++) {
                ulonglong2 wp = ws2[c*12 + q];
                fma2(acc2[q*2+0], xv2, wp.x);
                fma2(acc2[q*2+1], xv2, wp.y);
            }
        }
    }

    float m = -1e30f;
    #pragma unroll
    for (int q = 0; q < 24; q++) {
        float2 a = unpack2(acc2[q]);
        int j = 2*q;
        m = fmaxf(m, fmaxf(10.f * (a.x * s.sgd[j] + s.sbd[j]),
                           10.f * (a.y * s.sgd[j+1] + s.sbd[j+1])));
    }
    const float lstep = 0.08711371545f;  // ln(60)/47
    float sum = 0.f, dsum = 0.f;
    #pragma unroll
    for (int q = 0; q < 24; q++) {
        float2 a = unpack2(acc2[q]);
        int j = 2*q;
        float l0 = 10.f * (a.x * s.sgd[j]   + s.sbd[j]);
        float l1 = 10.f * (a.y * s.sgd[j+1] + s.sbd[j+1]);
        float e0 = __expf(l0 - m);
        float e1 = __expf(l1 - m);
        sum  += e0 + e1;
        dsum += e0 * __expf((float)j * lstep) + e1 * __expf((float)(j+1) * lstep);
    }
    float depth = dsum / sum;
    depth = fminf(fmaxf(depth, 1.0f), 65.0f);

    const float* K = intr + b * 9;
    float a00=K[0],a01=K[1],a02=K[2],a10=K[3],a11=K[4],a12=K[5],a20=K[6],a21=K[7],a22=K[8];
    float det = a00*(a11*a22 - a12*a21) - a01*(a10*a22 - a12*a20) + a02*(a10*a21 - a11*a20);
    float id = 1.0f / det;
    float i00 = (a11*a22 - a12*a21) * id;
    float i01 = (a02*a21 - a01*a22) * id;
    float i02 = (a01*a12 - a02*a11) * id;
    float i10 = (a12*a20 - a10*a22) * id;
    float i11 = (a00*a22 - a02*a20) * id;
    float i12 = (a02*a10 - a00*a12) * id;
    float i20 = (a10*a21 - a11*a20) * id;
    float i21 = (a01*a20 - a00*a21) * id;
    float i22 = (a00*a11 - a01*a10) * id;

    float py = (float)(p / W5i);
    float px = (float)(p - (p / W5i) * W5i);
    float cx = depth * (i00*px + i01*py + i02);
    float cy = depth * (i10*px + i11*py + i12);
    float cz = depth * (i20*px + i21*py + i22);

    const float* T = extr + b * 16;
    float ex = T[0]*cx + T[1]*cy + T[2]*cz  + T[3];
    float ey = T[4]*cx + T[5]*cy + T[6]*cz  + T[7];
    float ez = T[8]*cx + T[9]*cy + T[10]*cz + T[11];

    bool ev = (ex >= -51.2f) & (ex < 51.2f) & (ey >= -51.2f) & (ey < 51.2f)
            & (ez >= -5.0f)  & (ez < 3.0f);
    int bx = (int)floorf(ex / 0.4f + 64.0f);
    int by = (int)floorf(ey / 0.4f + 64.0f);
    bool gv = (bx >= 0) & (bx < 128) & (by >= 0) & (by < 128);

    int idx = -1; float wf = 0.f;
    if (ev & gv) {
        idx = ((b * 128 + by) * 128 + bx) * BEVC;
        wf = __expf(-0.05f * fabsf(ez));
    }
    g_sidx[b * N5 + p] = idx;
    g_swf [b * N5 + p] = wf;
}

__device__ void roleA(int bid, int tid, SmemA& s,
                      const float* __restrict__ stage1,
                      const float* __restrict__ w1, const float* __restrict__ g1,
                      const float* __restrict__ b1,
                      const float* __restrict__ w2, const float* __restrict__ g2,
                      const float* __restrict__ b2,
                      float* __restrict__ skip_out)
{
    for (int i = tid; i < 64*64; i += 128) { int o = i & 63, c = i >> 6; s.w1T[c*64+o] = w1[o*64+c]; }
    for (int i = tid; i < 64*32; i += 128) { int q = i & 31, o = i >> 5; s.w2T[o*32+q] = w2[q*64+o]; }
    if (tid < 64) { s.sg1[tid] = g1[tid]; s.sb1[tid] = b1[tid]; }
    if (tid < 32) { s.sg2[tid] = g2[tid]; s.sb2[tid] = b2[tid]; }
    __syncthreads();

    int gid = bid * 256 + tid;
    int b = gid / HW1;
    int p = gid - b * HW1;
    const float* xin = stage1 + (size_t)b * 64 * HW1 + p;

    u64 acc[2][32];
    #pragma unroll
    for (int q = 0; q < 32; q++) { acc[0][q] = 0ull; acc[1][q] = 0ull; }

    const ulonglong2* w1T2 = (const ulonglong2*)s.w1T;
    for (int c = 0; c < 64; c++) {
        const float* xc = xin + (size_t)c * HW1;
        u64 x0 = pack2(xc[0],   xc[0]);
        u64 x1 = pack2(xc[128], xc[128]);
        #pragma unroll
        for (int q = 0; q < 16; q++) {
            ulonglong2 wp = w1T2[c*16 + q];
            fma2(acc[0][q*2+0], x0, wp.x);
            fma2(acc[0][q*2+1], x0, wp.y);
            fma2(acc[1][q*2+0], x1, wp.x);
            fma2(acc[1][q*2+1], x1, wp.y);
        }
    }

    const ulonglong2* w2T2 = (const ulonglong2*)s.w2T;
    #pragma unroll
    for (int px = 0; px < 2; px++) {
        u64 sacc2[16];
        #pragma unroll
        for (int q = 0; q < 16; q++) sacc2[q] = 0ull;
        #pragma unroll
        for (int q = 0; q < 32; q++) {
            float2 a = unpack2(acc[px][q]);
            int o = 2*q;
            float v0 = fmaxf(a.x * s.sg1[o]   + s.sb1[o],   0.f);
            float v1 = fmaxf(a.y * s.sg1[o+1] + s.sb1[o+1], 0.f);
            u64 v0p = pack2(v0, v0);
            u64 v1p = pack2(v1, v1);
            #pragma unroll
            for (int s4 = 0; s4 < 8; s4++) {
                ulonglong2 wp0 = w2T2[o*8 + s4];
                fma2(sacc2[s4*2+0], v0p, wp0.x);
                fma2(sacc2[s4*2+1], v0p, wp0.y);
            }
            #pragma unroll
            for (int s4 = 0; s4 < 8; s4++) {
                ulonglong2 wp1 = w2T2[(o+1)*8 + s4];
                fma2(sacc2[s4*2+0], v1p, wp1.x);
                fma2(sacc2[s4*2+1], v1p, wp1.y);
            }
        }
        float* op = skip_out + (size_t)b * 32 * HW1 + p + px * 128;
        #pragma unroll
        for (int q = 0; q < 16; q++) {
            float2 a = unpack2(sacc2[q]);
            op[(size_t)(2*q+0) * HW1] = fmaxf(a.x * s.sg2[2*q+0] + s.sb2[2*q+0], 0.f);
            op[(size_t)(2*q+1) * HW1] = fmaxf(a.y * s.sg2[2*q+1] + s.sb2[2*q+1], 0.f);
        }
    }
}

__global__ __launch_bounds__(128)
void kFused1(const float* __restrict__ stage1,
             const float* __restrict__ stage5,
             const float* __restrict__ intr, const float* __restrict__ extr,
             const float* __restrict__ red1_w, const float* __restrict__ red1_g, const float* __restrict__ red1_b,
             const float* __restrict__ skip_w, const float* __restrict__ skip_g, const float* __restrict__ skip_b,
             const float* __restrict__ dep5_w, const float* __restrict__ dep5_g, const float* __restrict__ dep5_b,
             const float* __restrict__ main_w,
             float* __restrict__ skip_out)
{
    __shared__ SmemU su;
    int tid = threadIdx.x;
    int bid = blockIdx.x;
    if (bid < ROLEW_BLKS) {
        roleW(bid, tid, main_w);
    } else if (bid < ROLEW_BLKS + ROLEB_BLKS) {
        roleB(bid - ROLEW_BLKS, tid, su.b, stage5, dep5_w, dep5_g, dep5_b, intr, extr);
    } else {
        roleA(bid - ROLEW_BLKS - ROLEB_BLKS, tid, su.a, stage1,
              red1_w, red1_g, red1_b, skip_w, skip_g, skip_b, skip_out);
    }
}

// ---------------------------------------------------------------------------
// Kernel B2: reduced-feature GEMM (64 out) + scatter-add, 2 pixels/thread.
// ---------------------------------------------------------------------------
__global__ __launch_bounds__(128, 2)
void kB2(const float* __restrict__ stage5,
         const float* __restrict__ w5, const float* __restrict__ g5, const float* __restrict__ b5)
{
    __shared__ __align__(16) float ws[64*64];   // [c][o]
    __shared__ float sg[64], sb[64];
    int tid = threadIdx.x;
    if (tid < 64) { sg[tid] = g5[tid]; sb[tid] = b5[tid]; }
    int b = blockIdx.x / 44;
    int p = (blockIdx.x - b * 44) * 256 + tid;
    const float* xin = stage5 + (size_t)b * 512 * N5 + p;

    u64 acc[2][32];
    #pragma unroll
    for (int q = 0; q < 32; q++) { acc[0][q] = 0ull; acc[1][q] = 0ull; }

    for (int c0 = 0; c0 < 512; c0 += 64) {
        __syncthreads();
        for (int i = tid; i < 64*64; i += 128) {
            int o = i & 63; int c = i >> 6;
            ws[c*64 + o] = w5[o*512 + c0 + c];
        }
        __syncthreads();
        const ulonglong2* ws2 = (const ulonglong2*)ws;
        for (int c = 0; c < 64; c++) {
            const float* xc = xin + (size_t)(c0 + c) * N5;
            u64 x0 = pack2(xc[0],   xc[0]);
            u64 x1 = pack2(xc[128], xc[128]);
            #pragma unroll
            for (int q = 0; q < 16; q++) {
                ulonglong2 wp = ws2[c*16 + q];
                fma2(acc[0][q*2+0], x0, wp.x);
                fma2(acc[0][q*2+1], x0, wp.y);
                fma2(acc[1][q*2+0], x1, wp.x);
                fma2(acc[1][q*2+1], x1, wp.y);
            }
        }
    }

    #pragma unroll
    for (int px = 0; px < 2; px++) {
        int pp = p + px * 128;
        int idx = g_sidx[b * N5 + pp];
        float wf = g_swf[b * N5 + pp];
        if (idx >= 0) {
            float* cell = g_bev + idx;
            #pragma unroll
            for (int q = 0; q < 32; q++) {
                float2 a = unpack2(acc[px][q]);
                float r0 = fmaxf(a.x * sg[2*q+0] + sb[2*q+0], 0.f) * wf;
                float r1 = fmaxf(a.y * sg[2*q+1] + sb[2*q+1], 0.f) * wf;
                atomicAdd(cell + 2*q+0, r0);
                atomicAdd(cell + 2*q+1, r1);
            }
        }
    }
}

// ---------------------------------------------------------------------------
// Kernel C v2: 3x3 conv (64->128) + BN + ReLU.
// 32x16 spatial tile, 64 oc per block, 2 px/thread (64 FMA2 chains),
// per-kk weight staging (double-buffered) from transposed g_wt.
// ---------------------------------------------------------------------------
__global__ __launch_bounds__(256)
void kC(const float* __restrict__ g, const float* __restrict__ bb,
        float* __restrict__ out)
{
    extern __shared__ __align__(16) float sm[];
    float* sin_ = sm;               // [ic 64][cell 612]  (18 x 34 tile)
    float* wbuf = sm + 64*612;      // [2][ic 64][oc 64]
    int tid = threadIdx.x;
    int tx = tid & 31, ty = tid >> 5;        // ty 0..7
    int x0 = blockIdx.x * 32, y0 = blockIdx.y * 16;
    int bz = blockIdx.z;
    int b = bz >> 1;
    int oc0 = (bz & 1) * 64;

    // input tile (with halo, zero padded) -> shared
    const float4* bev4 = (const float4*)g_bev;
    for (int i = tid; i < 612*16; i += 256) {
        int icg = i & 15;
        int cell = i >> 4;
        int iy = cell / 34, ix = cell - iy * 34;
        int gy = y0 + iy - 1, gx = x0 + ix - 1;
        float4 v = make_float4(0.f, 0.f, 0.f, 0.f);
        if (gy >= 0 && gy < 128 && gx >= 0 && gx < 128)
            v = bev4[((((size_t)b * 128 + gy) * 128 + gx) << 4) + icg];
        sin_[(icg*4+0)*612 + cell] = v.x;
        sin_[(icg*4+1)*612 + cell] = v.y;
        sin_[(icg*4+2)*612 + cell] = v.z;
        sin_[(icg*4+3)*612 + cell] = v.w;
    }
    // stage kk=0 weights
    for (int i = tid; i < 4096; i += 256)
        wbuf[i] = g_wt[((i >> 6) << 7) + oc0 + (i & 63)];   // (0*64+ic)*128 + oc0+oc
    __syncthreads();

    u64 acc[2][32];
    #pragma unroll
    for (int q = 0; q < 32; q++) { acc[0][q] = 0ull; acc[1][q] = 0ull; }

    for (int kk = 0; kk < 9; kk++) {
        int buf = kk & 1;
        if (kk < 8) {
            int nb = buf ^ 1;
            for (int i = tid; i < 4096; i += 256)
                wbuf[nb*4096 + i] = g_wt[(((kk+1)*64 + (i >> 6)) << 7) + oc0 + (i & 63)];
        }
        int ky = kk / 3, kx = kk - ky*3;
        int base0 = (ty + ky) * 34 + tx + kx;
        int base1 = base0 + 8 * 34;
        const ulonglong2* wb = (const ulonglong2*)(wbuf + buf*4096);
        for (int ic = 0; ic < 64; ic++) {
            float xv0 = sin_[ic * 612 + base0];
            float xv1 = sin_[ic * 612 + base1];
            u64 x0p = pack2(xv0, xv0);
            u64 x1p = pack2(xv1, xv1);
            const ulonglong2* wrow = wb + ic*16;
            #pragma unroll
            for (int q = 0; q < 16; q++) {
                ulonglong2 wv = wrow[q];
                fma2(acc[0][2*q+0], x0p, wv.x);
                fma2(acc[0][2*q+1], x0p, wv.y);
                fma2(acc[1][2*q+0], x1p, wv.x);
                fma2(acc[1][2*q+1], x1p, wv.y);
            }
        }
        __syncthreads();
    }

    #pragma unroll
    for (int px = 0; px < 2; px++) {
        float* op = out + (((size_t)b * 128 + oc0) * 128 + (y0 + ty + px*8)) * 128 + (x0 + tx);
        #pragma unroll
        for (int q = 0; q < 32; q++) {
            float2 a = unpack2(acc[px][q]);
            int o = 2*q;
            op[(size_t)(o+0) * 16384] = fmaxf(a.x * g[oc0 + o]     + bb[oc0 + o],     0.f);
            op[(size_t)(o+1) * 16384] = fmaxf(a.y * g[oc0 + o + 1] + bb[oc0 + o + 1], 0.f);
        }
    }
}

// ---------------------------------------------------------------------------
extern "C" void kernel_launch(void* const* d_in, const int* in_sizes, int n_in,
                              void* d_out, int out_size)
{
    const float* stage1 = (const float*)d_in[0];
    const float* stage5 = (const float*)d_in[1];
    const float* intr   = (const float*)d_in[2];
    const float* extr   = (const float*)d_in[3];
    const float* red1_w = (const float*)d_in[4];
    const float* red1_g = (const float*)d_in[5];
    const float* red1_b = (const float*)d_in[6];
    const float* skip_w = (const float*)d_in[7];
    const float* skip_g = (const float*)d_in[8];
    const float* skip_b = (const float*)d_in[9];
    const float* red5_w = (const float*)d_in[10];
    const float* red5_g = (const float*)d_in[11];
    const float* red5_b = (const float*)d_in[12];
    const float* dep5_w = (const float*)d_in[13];
    const float* dep5_g = (const float*)d_in[14];
    const float* dep5_b = (const float*)d_in[15];
    const float* main_w = (const float*)d_in[16];
    const float* main_g = (const float*)d_in[17];
    const float* main_b = (const float*)d_in[18];

    float* out_main = (float*)d_out;
    float* out_skip = (float*)d_out + OUT_MAIN;

    // zero BEV scratch
    void* bevPtr = nullptr;
    cudaGetSymbolAddress(&bevPtr, g_bev);
    cudaMemsetAsync(bevPtr, 0, sizeof(float) * (size_t)Bn * 128 * 128 * BEVC);

    // fused: weight transpose + depth head + skip path (co-resident)
    kFused1<<<ROLEW_BLKS + ROLEB_BLKS + ROLEA_BLKS, 128>>>(
        stage1, stage5, intr, extr,
        red1_w, red1_g, red1_b, skip_w, skip_g, skip_b,
        dep5_w, dep5_g, dep5_b, main_w, out_skip);

    // reduced features + scatter (2 px/thread)
    kB2<<<Bn * 44, 128>>>(stage5, red5_w, red5_g, red5_b);

    // BEV conv (32x16 tile, 64 oc/block, per-kk weight staging)
    int smem = (64*612 + 2*4096) * sizeof(float);   // 189440
    cudaFuncSetAttribute(kC, cudaFuncAttributeMaxDynamicSharedMemorySize, smem);
    dim3 gridC(4, 8, Bn * 2);
    kC<<<gridC, 256, smem>>>(main_g, main_b, out_main);
}